// round 3
// baseline (speedup 1.0000x reference)
#include <cuda_runtime.h>

#define NN 50000
#define EE 800000
#define HD 128
#define NH 4
#define ND 32

// ---------------- scratch (device globals; no allocation allowed) ----------
__device__ float g_feat[NN * HD];   // Wh for current layer
__device__ float g_el[NN * NH];     // a_l . Wh
__device__ float g_er[NN * NH];     // a_r . Wh
__device__ float g_m[NN * NH];      // segment max
__device__ float g_den[NN * NH];    // segment sum of exp
__device__ float g_acc[NN * HD];    // aggregated output (pre-ELU)
__device__ float g_e[EE * NH];      // edge logits, then exp(e - m)
__device__ float g_h1[NN * HD];     // layer-1 output (post-ELU)
__device__ int   g_srci[EE];        // decoded int32 src
__device__ int   g_dsti[EE];        // decoded int32 dst
__device__ int   g_is64;            // 1 if src/dst stored as int64

// ---------------- helpers ---------------------------------------------------
__device__ __forceinline__ void atomicMaxF(float* addr, float v) {
    if (v >= 0.f) atomicMax((int*)addr, __float_as_int(v));
    else          atomicMin((unsigned int*)addr, __float_as_uint(v));
}

__device__ __forceinline__ void redAddV4(float* addr, float4 v) {
    asm volatile("red.global.add.v4.f32 [%0], {%1, %2, %3, %4};"
                 :: "l"(addr), "f"(v.x), "f"(v.y), "f"(v.z), "f"(v.w)
                 : "memory");
}

__device__ __forceinline__ float lrelu(float x) {
    return (x > 0.f) ? x : 0.2f * x;
}

// Detect int64 vs int32 edge indices: int32 data misread as int64 packs two
// random node ids -> value >= 2^32 almost surely.
__global__ void detect_kernel(const long long* __restrict__ src) {
    if (threadIdx.x == 0 && blockIdx.x == 0) {
        bool is64 = true;
        for (int i = 0; i < 8; i++) {
            long long v = src[i];
            if (v < 0 || v >= NN) { is64 = false; break; }
        }
        g_is64 = is64 ? 1 : 0;
    }
}

__global__ void convert_kernel(const void* __restrict__ src,
                               const void* __restrict__ dst) {
    int e = blockIdx.x * blockDim.x + threadIdx.x;
    if (e >= EE) return;
    if (g_is64) {
        g_srci[e] = (int)((const long long*)src)[e];
        g_dsti[e] = (int)((const long long*)dst)[e];
    } else {
        g_srci[e] = ((const int*)src)[e];
        g_dsti[e] = ((const int*)dst)[e];
    }
}

// ---------------- GEMM: feat = x @ W^T, plus el/er epilogue -----------------
// Block = 128 threads (thread j owns output column j; warp w == head w).
// W row j (128 floats) lives in registers; x rows broadcast from smem.
// xin == nullptr means "read layer-1 output g_h1" (device symbol must be
// referenced from device code only).
#define NPB 8
__global__ void __launch_bounds__(128) gemm_kernel(
    const float* __restrict__ xin, const float* __restrict__ W,
    const float* __restrict__ al, const float* __restrict__ ar)
{
    __shared__ float xs[NPB][HD];
    const float* xp = xin ? xin : (const float*)g_h1;
    const int j = threadIdx.x;
    const int node0 = blockIdx.x * NPB;

    float w[HD];
    const float4* W4 = (const float4*)(W + j * HD);
#pragma unroll
    for (int k = 0; k < HD / 4; k++) {
        float4 v = W4[k];
        w[4 * k + 0] = v.x; w[4 * k + 1] = v.y;
        w[4 * k + 2] = v.z; w[4 * k + 3] = v.w;
    }
    const float a_l = al[j];
    const float a_r = ar[j];

    for (int i = threadIdx.x; i < NPB * HD; i += 128) {
        int n = i >> 7, k = i & (HD - 1);
        int node = node0 + n;
        xs[n][k] = (node < NN) ? xp[node * HD + k] : 0.f;
    }
    __syncthreads();

    const int warp = j >> 5, lane = j & 31;
    for (int n = 0; n < NPB; n++) {
        int node = node0 + n;
        if (node >= NN) break;
        float acc = 0.f;
        const float4* xv = (const float4*)xs[n];
#pragma unroll
        for (int k = 0; k < HD / 4; k++) {
            float4 v = xv[k];
            acc = fmaf(v.x, w[4 * k + 0], acc);
            acc = fmaf(v.y, w[4 * k + 1], acc);
            acc = fmaf(v.z, w[4 * k + 2], acc);
            acc = fmaf(v.w, w[4 * k + 3], acc);
        }
        g_feat[node * HD + j] = acc;
        float pl = acc * a_l;
        float pr = acc * a_r;
#pragma unroll
        for (int off = 16; off; off >>= 1) {
            pl += __shfl_down_sync(0xffffffffu, pl, off);
            pr += __shfl_down_sync(0xffffffffu, pr, off);
        }
        if (lane == 0) {
            g_el[node * NH + warp] = pl;
            g_er[node * NH + warp] = pr;
        }
    }
}

// ---------------- init: acc=0, m=-inf, den=0 --------------------------------
__global__ void init_kernel() {
    int i = blockIdx.x * blockDim.x + threadIdx.x;
    if (i < NN * HD) g_acc[i] = 0.f;
    if (i < NN * NH) {
        g_m[i] = __int_as_float(0xff800000);  // -inf
        g_den[i] = 0.f;
    }
}

// ---------------- edge pass 1: logits + segment max (1 thread = 1 edge) -----
__global__ void edge_logit_kernel() {
    int e = blockIdx.x * blockDim.x + threadIdx.x;
    if (e >= EE) return;
    int s = g_srci[e], t = g_dsti[e];
    float4 l4 = *(const float4*)(g_el + s * NH);
    float4 r4 = *(const float4*)(g_er + t * NH);
    float4 v;
    v.x = lrelu(l4.x + r4.x);
    v.y = lrelu(l4.y + r4.y);
    v.z = lrelu(l4.z + r4.z);
    v.w = lrelu(l4.w + r4.w);
    *(float4*)(g_e + e * NH) = v;
    atomicMaxF(&g_m[t * NH + 0], v.x);
    atomicMaxF(&g_m[t * NH + 1], v.y);
    atomicMaxF(&g_m[t * NH + 2], v.z);
    atomicMaxF(&g_m[t * NH + 3], v.w);
}

// ---------------- edge pass 2: exp + segment sum ----------------------------
__global__ void edge_exp_kernel() {
    int e = blockIdx.x * blockDim.x + threadIdx.x;
    if (e >= EE) return;
    int t = g_dsti[e];
    float4 v = *(const float4*)(g_e + e * NH);
    float4 m4 = *(const float4*)(g_m + t * NH);
    v.x = __expf(v.x - m4.x);
    v.y = __expf(v.y - m4.y);
    v.z = __expf(v.z - m4.z);
    v.w = __expf(v.w - m4.w);
    *(float4*)(g_e + e * NH) = v;
    redAddV4(&g_den[t * NH], v);
}

// ---------------- edge pass 3: weighted scatter-aggregate -------------------
// One warp per edge; lane handles 4 consecutive features (h = lane/8).
__global__ void __launch_bounds__(256) aggregate_kernel() {
    int e = blockIdx.x * 8 + (threadIdx.x >> 5);
    if (e >= EE) return;
    int lane = threadIdx.x & 31;
    int s = g_srci[e], t = g_dsti[e];
    float4 ve = *(const float4*)(g_e + e * NH);      // warp-broadcast
    float4 vd = *(const float4*)(g_den + t * NH);    // warp-broadcast
    int h = lane >> 3;
    float num = (h == 0) ? ve.x : (h == 1) ? ve.y : (h == 2) ? ve.z : ve.w;
    float den = (h == 0) ? vd.x : (h == 1) ? vd.y : (h == 2) ? vd.z : vd.w;
    float alpha = __fdividef(num, den);
    float4 f = *(const float4*)(g_feat + s * HD + lane * 4);
    f.x *= alpha; f.y *= alpha; f.z *= alpha; f.w *= alpha;
    redAddV4(&g_acc[t * HD + lane * 4], f);
}

// ---------------- ELU (layer 1 -> g_h1) -------------------------------------
__global__ void elu1_kernel() {
    int i = blockIdx.x * blockDim.x + threadIdx.x;
    if (i >= NN * HD) return;
    float x = g_acc[i];
    g_h1[i] = (x > 0.f) ? x : expm1f(x);
}

// ---------------- final: ELU + mean over heads -> out [N, D] ----------------
__global__ void final_kernel(float* __restrict__ out) {
    int i = blockIdx.x * blockDim.x + threadIdx.x;
    if (i >= NN * ND) return;
    int n = i / ND, d = i - n * ND;
    float ssum = 0.f;
#pragma unroll
    for (int h = 0; h < NH; h++) {
        float x = g_acc[n * HD + h * ND + d];
        ssum += (x > 0.f) ? x : expm1f(x);
    }
    out[i] = 0.25f * ssum;
}

// ---------------- launch ----------------------------------------------------
extern "C" void kernel_launch(void* const* d_in, const int* in_sizes, int n_in,
                              void* d_out, int out_size)
{
    const float* x   = (const float*)d_in[0];
    const void*  src = d_in[1];
    const void*  dst = d_in[2];
    const float* W1  = (const float*)d_in[3];
    const float* al1 = (const float*)d_in[4];
    const float* ar1 = (const float*)d_in[5];
    const float* W2  = (const float*)d_in[6];
    const float* al2 = (const float*)d_in[7];
    const float* ar2 = (const float*)d_in[8];
    float* out = (float*)d_out;

    const int gemm_blocks = (NN + NPB - 1) / NPB;
    const int init_blocks = (NN * HD + 255) / 256;
    const int edge_blocks = (EE + 255) / 256;
    const int aggr_blocks = (EE + 7) / 8;
    const int elu_blocks  = (NN * HD + 255) / 256;
    const int fin_blocks  = (NN * ND + 255) / 256;

    detect_kernel<<<1, 32>>>((const long long*)src);
    convert_kernel<<<edge_blocks, 256>>>(src, dst);

    // ---- layer 1 ----
    gemm_kernel<<<gemm_blocks, 128>>>(x, W1, al1, ar1);
    init_kernel<<<init_blocks, 256>>>();
    edge_logit_kernel<<<edge_blocks, 256>>>();
    edge_exp_kernel<<<edge_blocks, 256>>>();
    aggregate_kernel<<<aggr_blocks, 256>>>();
    elu1_kernel<<<elu_blocks, 256>>>();

    // ---- layer 2 ----
    gemm_kernel<<<gemm_blocks, 128>>>(nullptr, W2, al2, ar2);  // reads g_h1
    init_kernel<<<init_blocks, 256>>>();
    edge_logit_kernel<<<edge_blocks, 256>>>();
    edge_exp_kernel<<<edge_blocks, 256>>>();
    aggregate_kernel<<<aggr_blocks, 256>>>();
    final_kernel<<<fin_blocks, 256>>>(out);
}

// round 5
// speedup vs baseline: 1.4331x; 1.4331x over previous
#include <cuda_runtime.h>

#define NN 50000
#define EE 800000
#define HD 128
#define NH 4
#define ND 32
#define NEG_BIG (-3.0e38f)

// ---------------- scratch (device globals; no allocation allowed) ----------
__device__ float g_feat[NN * HD];   // Wh for current layer (25.6 MB)
__device__ float g_el[NN * NH];     // a_l . Wh
__device__ float g_er[NN * NH];     // a_r . Wh
__device__ float g_h1[NN * HD];     // layer-1 output (post-ELU) (25.6 MB)
__device__ int   g_dsti[EE];        // decoded int32 dst (3.2 MB)
__device__ int   g_csr_src[EE];     // src ids sorted by dst (3.2 MB)
__device__ int   g_cnt[NN];         // degree histogram, then scatter cursors
__device__ int   g_off[NN + 1];     // CSR offsets (by dst)
__device__ int   g_bsum[128];       // scan block sums
__device__ int   g_is64;            // 1 if src/dst stored as int64

// ---------------- helpers ---------------------------------------------------
__device__ __forceinline__ float lrelu(float x) {
    return (x > 0.f) ? x : 0.2f * x;
}

// Detect int64 vs int32 edge indices: int32 data misread as int64 packs two
// random node ids -> value out of [0, NN) almost surely.
__global__ void detect_kernel(const long long* __restrict__ src) {
    if (threadIdx.x == 0 && blockIdx.x == 0) {
        bool is64 = true;
        for (int i = 0; i < 8; i++) {
            long long v = src[i];
            if (v < 0 || v >= NN) { is64 = false; break; }
        }
        g_is64 = is64 ? 1 : 0;
    }
}

__global__ void zero_cnt_kernel() {
    int i = blockIdx.x * blockDim.x + threadIdx.x;
    if (i < NN) g_cnt[i] = 0;
}

// decode dst + degree histogram (src decoded later in scatter)
__global__ void convert_kernel(const void* __restrict__ dst) {
    int e = blockIdx.x * blockDim.x + threadIdx.x;
    if (e >= EE) return;
    int t = g_is64 ? (int)((const long long*)dst)[e] : ((const int*)dst)[e];
    g_dsti[e] = t;
    atomicAdd(&g_cnt[t], 1);
}

// ---------------- 3-kernel exclusive scan over g_cnt ------------------------
#define SCAN_B 512
__global__ void scan1_kernel() {
    __shared__ int sd[SCAN_B];
    int tid = threadIdx.x;
    int i = blockIdx.x * SCAN_B + tid;
    int v = (i < NN) ? g_cnt[i] : 0;
    sd[tid] = v;
    __syncthreads();
    for (int off = 1; off < SCAN_B; off <<= 1) {
        int t = (tid >= off) ? sd[tid - off] : 0;
        __syncthreads();
        sd[tid] += t;
        __syncthreads();
    }
    if (i < NN) g_off[i] = sd[tid] - v;          // exclusive
    if (tid == SCAN_B - 1) g_bsum[blockIdx.x] = sd[tid];
}

__global__ void scan2_kernel(int nblocks) {
    __shared__ int sd[128];
    int tid = threadIdx.x;
    int v = (tid < nblocks) ? g_bsum[tid] : 0;
    sd[tid] = v;
    __syncthreads();
    for (int off = 1; off < 128; off <<= 1) {
        int t = (tid >= off) ? sd[tid - off] : 0;
        __syncthreads();
        sd[tid] += t;
        __syncthreads();
    }
    if (tid < nblocks) g_bsum[tid] = sd[tid] - v;  // exclusive
}

__global__ void scan3_kernel() {
    int i = blockIdx.x * blockDim.x + threadIdx.x;
    if (i < NN) {
        int o = g_off[i] + g_bsum[i / SCAN_B];
        g_off[i] = o;
        g_cnt[i] = o;        // becomes scatter cursor
    }
    if (i == 0) g_off[NN] = EE;
}

__global__ void scatter_kernel(const void* __restrict__ src) {
    int e = blockIdx.x * blockDim.x + threadIdx.x;
    if (e >= EE) return;
    int s = g_is64 ? (int)((const long long*)src)[e] : ((const int*)src)[e];
    int t = g_dsti[e];
    int pos = atomicAdd(&g_cnt[t], 1);
    g_csr_src[pos] = s;
}

// ---------------- GEMM: feat = x @ W^T, plus el/er epilogue -----------------
// Block = 128 threads (thread j owns output column j; warp w == head w).
// W row j (128 floats) in registers; x rows broadcast from smem.
// xin == nullptr means "read layer-1 output g_h1".
#define NPB 16
__global__ void __launch_bounds__(128) gemm_kernel(
    const float* __restrict__ xin, const float* __restrict__ W,
    const float* __restrict__ al, const float* __restrict__ ar)
{
    __shared__ float xs[NPB][HD];
    const float* xp = xin ? xin : (const float*)g_h1;
    const int j = threadIdx.x;
    const int node0 = blockIdx.x * NPB;

    float w[HD];
    const float4* W4 = (const float4*)(W + j * HD);
#pragma unroll
    for (int k = 0; k < HD / 4; k++) {
        float4 v = W4[k];
        w[4 * k + 0] = v.x; w[4 * k + 1] = v.y;
        w[4 * k + 2] = v.z; w[4 * k + 3] = v.w;
    }
    const float a_l = al[j];
    const float a_r = ar[j];

    for (int i = threadIdx.x; i < NPB * HD; i += 128) {
        int n = i >> 7, k = i & (HD - 1);
        int node = node0 + n;
        xs[n][k] = (node < NN) ? xp[node * HD + k] : 0.f;
    }
    __syncthreads();

    const int warp = j >> 5, lane = j & 31;
    for (int n = 0; n < NPB; n++) {
        int node = node0 + n;
        if (node >= NN) break;
        float acc = 0.f;
        const float4* xv = (const float4*)xs[n];
#pragma unroll
        for (int k = 0; k < HD / 4; k++) {
            float4 v = xv[k];
            acc = fmaf(v.x, w[4 * k + 0], acc);
            acc = fmaf(v.y, w[4 * k + 1], acc);
            acc = fmaf(v.z, w[4 * k + 2], acc);
            acc = fmaf(v.w, w[4 * k + 3], acc);
        }
        g_feat[node * HD + j] = acc;
        float pl = acc * a_l;
        float pr = acc * a_r;
#pragma unroll
        for (int off = 16; off; off >>= 1) {
            pl += __shfl_down_sync(0xffffffffu, pl, off);
            pr += __shfl_down_sync(0xffffffffu, pr, off);
        }
        if (lane == 0) {
            g_el[node * NH + warp] = pl;
            g_er[node * NH + warp] = pr;
        }
    }
}

// ---------------- fused edge softmax + aggregate (warp per dst node) --------
// out == nullptr: layer 1 -> write elu(acc) to g_h1.
// else: layer 2 -> elu + mean over heads -> out [N, D].
__global__ void __launch_bounds__(256) gat_edge_kernel(float* __restrict__ out)
{
    int t = blockIdx.x * 8 + (threadIdx.x >> 5);
    if (t >= NN) return;
    const int lane = threadIdx.x & 31;
    const int beg = g_off[t], end = g_off[t + 1];
    const int h = lane >> 3;

    float4 acc = {0.f, 0.f, 0.f, 0.f};

    if (beg < end) {
        float4 er4 = *(const float4*)(g_er + t * NH);  // broadcast

        // ---- phase 1: online (max, denom) per head, lane-strided ----
        float4 m4 = {NEG_BIG, NEG_BIG, NEG_BIG, NEG_BIG};
        float4 d4 = {0.f, 0.f, 0.f, 0.f};
        for (int i = beg + lane; i < end; i += 32) {
            int s = __ldg(&g_csr_src[i]);
            float4 l4 = *(const float4*)(g_el + s * NH);
            float4 e4;
            e4.x = lrelu(l4.x + er4.x);
            e4.y = lrelu(l4.y + er4.y);
            e4.z = lrelu(l4.z + er4.z);
            e4.w = lrelu(l4.w + er4.w);
#define ONLINE(mc, dc, ec) { float mn = fmaxf(mc, ec); \
            dc = dc * __expf(mc - mn) + __expf(ec - mn); mc = mn; }
            ONLINE(m4.x, d4.x, e4.x)
            ONLINE(m4.y, d4.y, e4.y)
            ONLINE(m4.z, d4.z, e4.z)
            ONLINE(m4.w, d4.w, e4.w)
#undef ONLINE
        }
        // warp combine (m,d) pairs per component
#define COMBINE(mc, dc) \
        for (int off = 16; off; off >>= 1) { \
            float om = __shfl_xor_sync(0xffffffffu, mc, off); \
            float od = __shfl_xor_sync(0xffffffffu, dc, off); \
            float mn = fmaxf(mc, om); \
            dc = dc * __expf(mc - mn) + od * __expf(om - mn); \
            mc = mn; \
        }
        COMBINE(m4.x, d4.x)
        COMBINE(m4.y, d4.y)
        COMBINE(m4.z, d4.z)
        COMBINE(m4.w, d4.w)
#undef COMBINE
        float4 rd4;
        rd4.x = __frcp_rn(d4.x); rd4.y = __frcp_rn(d4.y);
        rd4.z = __frcp_rn(d4.z); rd4.w = __frcp_rn(d4.w);

        // ---- phase 2: chunked aggregation ----
        for (int base = beg; base < end; base += 32) {
            int n = min(32, end - base);
            int s_my = 0;
            float4 a4 = {0.f, 0.f, 0.f, 0.f};
            if (lane < n) {
                s_my = __ldg(&g_csr_src[base + lane]);
                float4 l4 = *(const float4*)(g_el + s_my * NH);
                a4.x = __expf(lrelu(l4.x + er4.x) - m4.x) * rd4.x;
                a4.y = __expf(lrelu(l4.y + er4.y) - m4.y) * rd4.y;
                a4.z = __expf(lrelu(l4.z + er4.z) - m4.z) * rd4.z;
                a4.w = __expf(lrelu(l4.w + er4.w) - m4.w) * rd4.w;
            }
            for (int i = 0; i < n; i++) {
                int si = __shfl_sync(0xffffffffu, s_my, i);
                float a0 = __shfl_sync(0xffffffffu, a4.x, i);
                float a1 = __shfl_sync(0xffffffffu, a4.y, i);
                float a2 = __shfl_sync(0xffffffffu, a4.z, i);
                float a3 = __shfl_sync(0xffffffffu, a4.w, i);
                float alpha = (h == 0) ? a0 : (h == 1) ? a1 : (h == 2) ? a2 : a3;
                float4 f = *(const float4*)(g_feat + si * HD + lane * 4);
                acc.x = fmaf(f.x, alpha, acc.x);
                acc.y = fmaf(f.y, alpha, acc.y);
                acc.z = fmaf(f.z, alpha, acc.z);
                acc.w = fmaf(f.w, alpha, acc.w);
            }
        }
    }

    // ---- epilogue: ELU (+ head-mean for layer 2) ----
    acc.x = (acc.x > 0.f) ? acc.x : expm1f(acc.x);
    acc.y = (acc.y > 0.f) ? acc.y : expm1f(acc.y);
    acc.z = (acc.z > 0.f) ? acc.z : expm1f(acc.z);
    acc.w = (acc.w > 0.f) ? acc.w : expm1f(acc.w);

    if (out == nullptr) {
        *(float4*)(g_h1 + t * HD + lane * 4) = acc;
    } else {
        // sum over heads: lanes l, l^8, l^16, l^24 hold same dims across heads
#pragma unroll
        for (int off = 8; off <= 16; off <<= 1) {
            acc.x += __shfl_xor_sync(0xffffffffu, acc.x, off);
            acc.y += __shfl_xor_sync(0xffffffffu, acc.y, off);
            acc.z += __shfl_xor_sync(0xffffffffu, acc.z, off);
            acc.w += __shfl_xor_sync(0xffffffffu, acc.w, off);
        }
        if (lane < 8) {
            float4 o;
            o.x = 0.25f * acc.x; o.y = 0.25f * acc.y;
            o.z = 0.25f * acc.z; o.w = 0.25f * acc.w;
            *(float4*)(out + t * ND + lane * 4) = o;
        }
    }
}

// ---------------- launch ----------------------------------------------------
extern "C" void kernel_launch(void* const* d_in, const int* in_sizes, int n_in,
                              void* d_out, int out_size)
{
    const float* x   = (const float*)d_in[0];
    const void*  src = d_in[1];
    const void*  dst = d_in[2];
    const float* W1  = (const float*)d_in[3];
    const float* al1 = (const float*)d_in[4];
    const float* ar1 = (const float*)d_in[5];
    const float* W2  = (const float*)d_in[6];
    const float* al2 = (const float*)d_in[7];
    const float* ar2 = (const float*)d_in[8];
    float* out = (float*)d_out;

    const int edge_blocks = (EE + 255) / 256;
    const int node_blocks = (NN + 255) / 256;
    const int scan_blocks = (NN + SCAN_B - 1) / SCAN_B;   // 98
    const int gemm_blocks = (NN + NPB - 1) / NPB;
    const int gat_blocks  = (NN + 7) / 8;

    // ---- CSR build ----
    detect_kernel<<<1, 32>>>((const long long*)src);
    zero_cnt_kernel<<<node_blocks, 256>>>();
    convert_kernel<<<edge_blocks, 256>>>(dst);
    scan1_kernel<<<scan_blocks, SCAN_B>>>();
    scan2_kernel<<<1, 128>>>(scan_blocks);
    scan3_kernel<<<node_blocks, 256>>>();
    scatter_kernel<<<edge_blocks, 256>>>(src);

    // ---- layer 1 ----
    gemm_kernel<<<gemm_blocks, 128>>>(x, W1, al1, ar1);
    gat_edge_kernel<<<gat_blocks, 256>>>(nullptr);

    // ---- layer 2 ----
    gemm_kernel<<<gemm_blocks, 128>>>(nullptr, W2, al2, ar2);
    gat_edge_kernel<<<gat_blocks, 256>>>(out);

    (void)in_sizes; (void)n_in; (void)out_size;
}

// round 6
// speedup vs baseline: 2.0762x; 1.4488x over previous
#include <cuda_runtime.h>

#define NN 50000
#define EE 800000
#define HD 128
#define NH 4
#define ND 32
#define NEG_BIG (-3.0e38f)

// ---------------- scratch (device globals; no allocation allowed) ----------
__device__ float g_feat[NN * HD];   // Wh for current layer (25.6 MB)
__device__ float g_el[NN * NH];     // a_l . Wh
__device__ float g_er[NN * NH];     // a_r . Wh
__device__ float g_h1[NN * HD];     // layer-1 output (post-ELU) (25.6 MB)
__device__ float g_e[EE * NH];      // exp(e - m) per edge, CSR order (12.8 MB)
__device__ int   g_dsti[EE];        // decoded int32 dst (3.2 MB)
__device__ int   g_csr_src[EE];     // src ids sorted by dst (3.2 MB)
__device__ int   g_cnt[NN];         // degree histogram, then scatter cursors
__device__ int   g_off[NN + 1];     // CSR offsets (by dst)
__device__ int   g_bsum[128];       // scan block sums
__device__ int   g_is64;            // 1 if src/dst stored as int64

// ---------------- helpers ---------------------------------------------------
__device__ __forceinline__ float lrelu(float x) {
    return (x > 0.f) ? x : 0.2f * x;
}

// Detect int64 vs int32 edge indices.
__global__ void detect_kernel(const long long* __restrict__ src) {
    if (threadIdx.x == 0 && blockIdx.x == 0) {
        bool is64 = true;
        for (int i = 0; i < 8; i++) {
            long long v = src[i];
            if (v < 0 || v >= NN) { is64 = false; break; }
        }
        g_is64 = is64 ? 1 : 0;
    }
}

__global__ void zero_cnt_kernel() {
    int i = blockIdx.x * blockDim.x + threadIdx.x;
    if (i < NN) g_cnt[i] = 0;
}

// decode dst + degree histogram
__global__ void convert_kernel(const void* __restrict__ dst) {
    int e = blockIdx.x * blockDim.x + threadIdx.x;
    if (e >= EE) return;
    int t = g_is64 ? (int)((const long long*)dst)[e] : ((const int*)dst)[e];
    g_dsti[e] = t;
    atomicAdd(&g_cnt[t], 1);
}

// ---------------- 3-kernel exclusive scan over g_cnt ------------------------
#define SCAN_B 512
__global__ void scan1_kernel() {
    __shared__ int sd[SCAN_B];
    int tid = threadIdx.x;
    int i = blockIdx.x * SCAN_B + tid;
    int v = (i < NN) ? g_cnt[i] : 0;
    sd[tid] = v;
    __syncthreads();
    for (int off = 1; off < SCAN_B; off <<= 1) {
        int t = (tid >= off) ? sd[tid - off] : 0;
        __syncthreads();
        sd[tid] += t;
        __syncthreads();
    }
    if (i < NN) g_off[i] = sd[tid] - v;          // exclusive
    if (tid == SCAN_B - 1) g_bsum[blockIdx.x] = sd[tid];
}

__global__ void scan2_kernel(int nblocks) {
    __shared__ int sd[128];
    int tid = threadIdx.x;
    int v = (tid < nblocks) ? g_bsum[tid] : 0;
    sd[tid] = v;
    __syncthreads();
    for (int off = 1; off < 128; off <<= 1) {
        int t = (tid >= off) ? sd[tid - off] : 0;
        __syncthreads();
        sd[tid] += t;
        __syncthreads();
    }
    if (tid < nblocks) g_bsum[tid] = sd[tid] - v;  // exclusive
}

__global__ void scan3_kernel() {
    int i = blockIdx.x * blockDim.x + threadIdx.x;
    if (i < NN) {
        int o = g_off[i] + g_bsum[i / SCAN_B];
        g_off[i] = o;
        g_cnt[i] = o;        // becomes scatter cursor
    }
    if (i == 0) g_off[NN] = EE;
}

__global__ void scatter_kernel(const void* __restrict__ src) {
    int e = blockIdx.x * blockDim.x + threadIdx.x;
    if (e >= EE) return;
    int s = g_is64 ? (int)((const long long*)src)[e] : ((const int*)src)[e];
    int t = g_dsti[e];
    int pos = atomicAdd(&g_cnt[t], 1);
    g_csr_src[pos] = s;
}

// ---------------- GEMM: feat = x @ W^T, plus el/er epilogue -----------------
// Block = 128 threads (thread j owns output column j; warp w == head w).
// W row j (128 floats) in registers; x rows broadcast from smem.
// xin == nullptr means "read layer-1 output g_h1".
#define NPB 32
__global__ void __launch_bounds__(128) gemm_kernel(
    const float* __restrict__ xin, const float* __restrict__ W,
    const float* __restrict__ al, const float* __restrict__ ar)
{
    __shared__ float xs[NPB][HD];
    const float* xp = xin ? xin : (const float*)g_h1;
    const int j = threadIdx.x;
    const int node0 = blockIdx.x * NPB;

    float w[HD];
    const float4* W4 = (const float4*)(W + j * HD);
#pragma unroll
    for (int k = 0; k < HD / 4; k++) {
        float4 v = W4[k];
        w[4 * k + 0] = v.x; w[4 * k + 1] = v.y;
        w[4 * k + 2] = v.z; w[4 * k + 3] = v.w;
    }
    const float a_l = al[j];
    const float a_r = ar[j];

    // stage NPB node rows (vectorized: NPB*HD/4 float4s by 128 threads)
    {
        const int nvec = NPB * HD / 4;           // float4 count
        float4* xsv = (float4*)xs;
        for (int i = threadIdx.x; i < nvec; i += 128) {
            int node = node0 + (i >> 5);          // HD/4 = 32 float4 per row
            xsv[i] = (node < NN) ? ((const float4*)xp)[(size_t)node * 32 + (i & 31)]
                                 : make_float4(0.f, 0.f, 0.f, 0.f);
        }
    }
    __syncthreads();

    const int warp = j >> 5, lane = j & 31;
    for (int n = 0; n < NPB; n++) {
        int node = node0 + n;
        if (node >= NN) break;
        float acc = 0.f;
        const float4* xv = (const float4*)xs[n];
#pragma unroll
        for (int k = 0; k < HD / 4; k++) {
            float4 v = xv[k];
            acc = fmaf(v.x, w[4 * k + 0], acc);
            acc = fmaf(v.y, w[4 * k + 1], acc);
            acc = fmaf(v.z, w[4 * k + 2], acc);
            acc = fmaf(v.w, w[4 * k + 3], acc);
        }
        g_feat[node * HD + j] = acc;
        float pl = acc * a_l;
        float pr = acc * a_r;
#pragma unroll
        for (int off = 16; off; off >>= 1) {
            pl += __shfl_down_sync(0xffffffffu, pl, off);
            pr += __shfl_down_sync(0xffffffffu, pr, off);
        }
        if (lane == 0) {
            g_el[node * NH + warp] = pl;
            g_er[node * NH + warp] = pr;
        }
    }
}

// ---------------- fused edge softmax + aggregate (warp per dst node) --------
// out == nullptr: layer 1 -> write elu(acc) to g_h1.
// else: layer 2 -> elu + mean over heads -> out [N, D].
__global__ void __launch_bounds__(256) gat_edge_kernel(float* __restrict__ out)
{
    __shared__ int   ssrc[8][32];
    __shared__ float salpha[8][32][4];

    const int w = threadIdx.x >> 5;
    int t = blockIdx.x * 8 + w;
    if (t >= NN) return;
    const int lane = threadIdx.x & 31;
    const int beg = g_off[t], end = g_off[t + 1];
    const int h = lane >> 3;

    float4 acc = {0.f, 0.f, 0.f, 0.f};

    if (beg < end) {
        float4 er4 = *(const float4*)(g_er + t * NH);  // broadcast

        // ---- phase 1a: plain max per head (no exp) ----
        float4 m4 = {NEG_BIG, NEG_BIG, NEG_BIG, NEG_BIG};
        for (int i = beg + lane; i < end; i += 32) {
            int s = __ldg(&g_csr_src[i]);
            float4 l4 = *(const float4*)(g_el + s * NH);
            m4.x = fmaxf(m4.x, lrelu(l4.x + er4.x));
            m4.y = fmaxf(m4.y, lrelu(l4.y + er4.y));
            m4.z = fmaxf(m4.z, lrelu(l4.z + er4.z));
            m4.w = fmaxf(m4.w, lrelu(l4.w + er4.w));
        }
#pragma unroll
        for (int off = 16; off; off >>= 1) {
            m4.x = fmaxf(m4.x, __shfl_xor_sync(0xffffffffu, m4.x, off));
            m4.y = fmaxf(m4.y, __shfl_xor_sync(0xffffffffu, m4.y, off));
            m4.z = fmaxf(m4.z, __shfl_xor_sync(0xffffffffu, m4.z, off));
            m4.w = fmaxf(m4.w, __shfl_xor_sync(0xffffffffu, m4.w, off));
        }

        // ---- phase 1b: ex = exp(e-m); stash to g_e (CSR order); sum denom --
        float4 d4 = {0.f, 0.f, 0.f, 0.f};
        for (int i = beg + lane; i < end; i += 32) {
            int s = __ldg(&g_csr_src[i]);
            float4 l4 = *(const float4*)(g_el + s * NH);
            float4 ex;
            ex.x = __expf(lrelu(l4.x + er4.x) - m4.x);
            ex.y = __expf(lrelu(l4.y + er4.y) - m4.y);
            ex.z = __expf(lrelu(l4.z + er4.z) - m4.z);
            ex.w = __expf(lrelu(l4.w + er4.w) - m4.w);
            d4.x += ex.x; d4.y += ex.y; d4.z += ex.z; d4.w += ex.w;
            *(float4*)(g_e + (size_t)i * NH) = ex;
        }
#pragma unroll
        for (int off = 16; off; off >>= 1) {
            d4.x += __shfl_xor_sync(0xffffffffu, d4.x, off);
            d4.y += __shfl_xor_sync(0xffffffffu, d4.y, off);
            d4.z += __shfl_xor_sync(0xffffffffu, d4.z, off);
            d4.w += __shfl_xor_sync(0xffffffffu, d4.w, off);
        }
        float4 rd4;
        rd4.x = __frcp_rn(d4.x); rd4.y = __frcp_rn(d4.y);
        rd4.z = __frcp_rn(d4.z); rd4.w = __frcp_rn(d4.w);

        // ---- phase 2: chunked aggregation via smem-staged (src, alpha) ----
        for (int base = beg; base < end; base += 32) {
            int n = min(32, end - base);
            if (lane < n) {
                int i = base + lane;
                int s = __ldg(&g_csr_src[i]);
                float4 ex = *(const float4*)(g_e + (size_t)i * NH);
                ssrc[w][lane] = s;
                salpha[w][lane][0] = ex.x * rd4.x;
                salpha[w][lane][1] = ex.y * rd4.y;
                salpha[w][lane][2] = ex.z * rd4.z;
                salpha[w][lane][3] = ex.w * rd4.w;
            }
            __syncwarp();
            for (int i = 0; i < n; i++) {
                int si = ssrc[w][i];
                float alpha = salpha[w][i][h];
                float4 f = *(const float4*)(g_feat + (size_t)si * HD + lane * 4);
                acc.x = fmaf(f.x, alpha, acc.x);
                acc.y = fmaf(f.y, alpha, acc.y);
                acc.z = fmaf(f.z, alpha, acc.z);
                acc.w = fmaf(f.w, alpha, acc.w);
            }
            __syncwarp();
        }
    }

    // ---- epilogue: ELU (+ head-mean for layer 2) ----
    acc.x = (acc.x > 0.f) ? acc.x : expm1f(acc.x);
    acc.y = (acc.y > 0.f) ? acc.y : expm1f(acc.y);
    acc.z = (acc.z > 0.f) ? acc.z : expm1f(acc.z);
    acc.w = (acc.w > 0.f) ? acc.w : expm1f(acc.w);

    if (out == nullptr) {
        *(float4*)(g_h1 + (size_t)t * HD + lane * 4) = acc;
    } else {
        // sum over heads: lanes l, l^8, l^16, l^24 hold same dims across heads
#pragma unroll
        for (int off = 8; off <= 16; off <<= 1) {
            acc.x += __shfl_xor_sync(0xffffffffu, acc.x, off);
            acc.y += __shfl_xor_sync(0xffffffffu, acc.y, off);
            acc.z += __shfl_xor_sync(0xffffffffu, acc.z, off);
            acc.w += __shfl_xor_sync(0xffffffffu, acc.w, off);
        }
        if (lane < 8) {
            float4 o;
            o.x = 0.25f * acc.x; o.y = 0.25f * acc.y;
            o.z = 0.25f * acc.z; o.w = 0.25f * acc.w;
            *(float4*)(out + t * ND + lane * 4) = o;
        }
    }
}

// ---------------- launch ----------------------------------------------------
extern "C" void kernel_launch(void* const* d_in, const int* in_sizes, int n_in,
                              void* d_out, int out_size)
{
    const float* x   = (const float*)d_in[0];
    const void*  src = d_in[1];
    const void*  dst = d_in[2];
    const float* W1  = (const float*)d_in[3];
    const float* al1 = (const float*)d_in[4];
    const float* ar1 = (const float*)d_in[5];
    const float* W2  = (const float*)d_in[6];
    const float* al2 = (const float*)d_in[7];
    const float* ar2 = (const float*)d_in[8];
    float* out = (float*)d_out;

    const int edge_blocks = (EE + 255) / 256;
    const int node_blocks = (NN + 255) / 256;
    const int scan_blocks = (NN + SCAN_B - 1) / SCAN_B;   // 98
    const int gemm_blocks = (NN + NPB - 1) / NPB;
    const int gat_blocks  = (NN + 7) / 8;

    // ---- CSR build ----
    detect_kernel<<<1, 32>>>((const long long*)src);
    zero_cnt_kernel<<<node_blocks, 256>>>();
    convert_kernel<<<edge_blocks, 256>>>(dst);
    scan1_kernel<<<scan_blocks, SCAN_B>>>();
    scan2_kernel<<<1, 128>>>(scan_blocks);
    scan3_kernel<<<node_blocks, 256>>>();
    scatter_kernel<<<edge_blocks, 256>>>(src);

    // ---- layer 1 ----
    gemm_kernel<<<gemm_blocks, 128>>>(x, W1, al1, ar1);
    gat_edge_kernel<<<gat_blocks, 256>>>(nullptr);

    // ---- layer 2 ----
    gemm_kernel<<<gemm_blocks, 128>>>(nullptr, W2, al2, ar2);
    gat_edge_kernel<<<gat_blocks, 256>>>(out);

    (void)in_sizes; (void)n_in; (void)out_size;
}

// round 7
// speedup vs baseline: 2.3098x; 1.1125x over previous
#include <cuda_runtime.h>

#define NN 50000
#define EE 800000
#define HD 128
#define NH 4
#define ND 32

typedef unsigned long long u64;

// ---------------- scratch (device globals; no allocation allowed) ----------
__device__ float g_feat[NN * HD];   // Wh for current layer (25.6 MB)
__device__ float g_el[NN * NH];     // a_l . Wh
__device__ float g_er[NN * NH];     // a_r . Wh
__device__ float g_h1[NN * HD];     // layer-1 output (post-ELU) (25.6 MB)
__device__ float g_e[EE * NH];      // exp(e) spill for deg>32 nodes (12.8 MB)
__device__ int   g_dsti[EE];        // decoded int32 dst (3.2 MB)
__device__ int   g_csr_src[EE];     // src ids sorted by dst (3.2 MB)
__device__ int   g_cnt[NN];         // degree histogram, then scatter cursors
__device__ int   g_off[NN + 1];     // CSR offsets (by dst)
__device__ int   g_bsum[128];       // scan block sums
__device__ int   g_is64;            // 1 if src/dst stored as int64

// ---------------- helpers ---------------------------------------------------
__device__ __forceinline__ float lrelu(float x) {
    return (x > 0.f) ? x : 0.2f * x;
}
__device__ __forceinline__ u64 fma2(u64 a, u64 b, u64 c) {
    u64 d;
    asm("fma.rn.f32x2 %0, %1, %2, %3;" : "=l"(d) : "l"(a), "l"(b), "l"(c));
    return d;
}
__device__ __forceinline__ u64 add2(u64 a, u64 b) {
    u64 d;
    asm("add.rn.f32x2 %0, %1, %2;" : "=l"(d) : "l"(a), "l"(b));
    return d;
}
__device__ __forceinline__ float sum2(u64 a) {
    float lo, hi;
    asm("mov.b64 {%0, %1}, %2;" : "=f"(lo), "=f"(hi) : "l"(a));
    return lo + hi;
}

// ---------------- CSR build --------------------------------------------------
// zero counters + detect int64 vs int32 edge indices (int32 misread as int64
// packs two random node ids -> out of [0, NN) almost surely).
__global__ void zero_cnt_kernel(const long long* __restrict__ src) {
    int i = blockIdx.x * blockDim.x + threadIdx.x;
    if (i < NN) g_cnt[i] = 0;
    if (i == 0) {
        bool is64 = true;
        for (int k = 0; k < 8; k++) {
            long long v = src[k];
            if (v < 0 || v >= NN) { is64 = false; break; }
        }
        g_is64 = is64 ? 1 : 0;
    }
}

// decode dst + degree histogram
__global__ void convert_kernel(const void* __restrict__ dst) {
    int e = blockIdx.x * blockDim.x + threadIdx.x;
    if (e >= EE) return;
    int t = g_is64 ? (int)((const long long*)dst)[e] : ((const int*)dst)[e];
    g_dsti[e] = t;
    atomicAdd(&g_cnt[t], 1);
}

#define SCAN_B 512
__global__ void scan1_kernel() {
    __shared__ int sd[SCAN_B];
    int tid = threadIdx.x;
    int i = blockIdx.x * SCAN_B + tid;
    int v = (i < NN) ? g_cnt[i] : 0;
    sd[tid] = v;
    __syncthreads();
    for (int off = 1; off < SCAN_B; off <<= 1) {
        int t = (tid >= off) ? sd[tid - off] : 0;
        __syncthreads();
        sd[tid] += t;
        __syncthreads();
    }
    if (i < NN) g_off[i] = sd[tid] - v;          // exclusive
    if (tid == SCAN_B - 1) g_bsum[blockIdx.x] = sd[tid];
}

__global__ void scan2_kernel(int nblocks) {
    __shared__ int sd[128];
    int tid = threadIdx.x;
    int v = (tid < nblocks) ? g_bsum[tid] : 0;
    sd[tid] = v;
    __syncthreads();
    for (int off = 1; off < 128; off <<= 1) {
        int t = (tid >= off) ? sd[tid - off] : 0;
        __syncthreads();
        sd[tid] += t;
        __syncthreads();
    }
    if (tid < nblocks) g_bsum[tid] = sd[tid] - v;  // exclusive
}

__global__ void scan3_kernel() {
    int i = blockIdx.x * blockDim.x + threadIdx.x;
    if (i < NN) {
        int o = g_off[i] + g_bsum[i / SCAN_B];
        g_off[i] = o;
        g_cnt[i] = o;        // becomes scatter cursor
    }
    if (i == 0) g_off[NN] = EE;
}

__global__ void scatter_kernel(const void* __restrict__ src) {
    int e = blockIdx.x * blockDim.x + threadIdx.x;
    if (e >= EE) return;
    int s = g_is64 ? (int)((const long long*)src)[e] : ((const int*)src)[e];
    int t = g_dsti[e];
    int pos = atomicAdd(&g_cnt[t], 1);
    g_csr_src[pos] = s;
}

// ---------------- GEMM: feat = x @ W^T, plus el/er epilogue -----------------
// Block = 128 threads (thread j owns output column j; warp w == head w).
// W row j in registers as 64 packed f32x2; x rows broadcast from smem.
// Inner product via fma.rn.f32x2 (half the FMA instructions of scalar FFMA).
// xin == nullptr means "read layer-1 output g_h1".
#define NPB 32
__global__ void __launch_bounds__(128) gemm_kernel(
    const float* __restrict__ xin, const float* __restrict__ W,
    const float* __restrict__ al, const float* __restrict__ ar)
{
    __shared__ float xs[NPB][HD];
    const float* xp = xin ? xin : (const float*)g_h1;
    const int j = threadIdx.x;
    const int node0 = blockIdx.x * NPB;

    u64 w2[HD / 2];
    const ulonglong2* Wv = (const ulonglong2*)(W + j * HD);
#pragma unroll
    for (int k = 0; k < HD / 4; k++) {
        ulonglong2 v = Wv[k];
        w2[2 * k + 0] = v.x;
        w2[2 * k + 1] = v.y;
    }
    const float a_l = al[j];
    const float a_r = ar[j];

    // stage NPB node rows (vectorized)
    {
        const int nvec = NPB * HD / 4;           // float4 count
        float4* xsv = (float4*)xs;
        for (int i = threadIdx.x; i < nvec; i += 128) {
            int node = node0 + (i >> 5);          // 32 float4 per row
            xsv[i] = (node < NN) ? ((const float4*)xp)[(size_t)node * 32 + (i & 31)]
                                 : make_float4(0.f, 0.f, 0.f, 0.f);
        }
    }
    __syncthreads();

    const int warp = j >> 5, lane = j & 31;
    for (int n = 0; n < NPB; n++) {
        int node = node0 + n;
        if (node >= NN) break;
        const ulonglong2* xv = (const ulonglong2*)xs[n];
        u64 a0 = 0ull, a1 = 0ull, a2 = 0ull, a3 = 0ull;  // {0.f,0.f} packed
#pragma unroll
        for (int k = 0; k < HD / 8; k++) {
            ulonglong2 xa = xv[2 * k + 0];
            ulonglong2 xb = xv[2 * k + 1];
            a0 = fma2(xa.x, w2[4 * k + 0], a0);
            a1 = fma2(xa.y, w2[4 * k + 1], a1);
            a2 = fma2(xb.x, w2[4 * k + 2], a2);
            a3 = fma2(xb.y, w2[4 * k + 3], a3);
        }
        float acc = sum2(add2(add2(a0, a1), add2(a2, a3)));
        g_feat[node * HD + j] = acc;
        float pl = acc * a_l;
        float pr = acc * a_r;
#pragma unroll
        for (int off = 16; off; off >>= 1) {
            pl += __shfl_down_sync(0xffffffffu, pl, off);
            pr += __shfl_down_sync(0xffffffffu, pr, off);
        }
        if (lane == 0) {
            g_el[node * NH + warp] = pl;
            g_er[node * NH + warp] = pr;
        }
    }
}

// ---------------- fused edge softmax + aggregate (warp per dst node) --------
// Softmax without max subtraction (|e| is small here; exp(e)/sum(exp(e)) is
// exactly the reference value mathematically).
// out == nullptr: layer 1 -> write elu(acc) to g_h1.
// else: layer 2 -> elu + mean over heads -> out [N, D].
__global__ void __launch_bounds__(256) gat_edge_kernel(float* __restrict__ out)
{
    __shared__ int   ssrc[8][32];
    __shared__ float salpha[8][32][4];

    const int w = threadIdx.x >> 5;
    int t = blockIdx.x * 8 + w;
    if (t >= NN) return;
    const int lane = threadIdx.x & 31;
    const int beg = g_off[t], end = g_off[t + 1];
    const int deg = end - beg;
    const int h = lane >> 3;

    float4 acc = {0.f, 0.f, 0.f, 0.f};

    if (deg > 0) {
        float4 er4 = *(const float4*)(g_er + t * NH);  // broadcast
        const bool small = (deg <= 32);

        // ---- phase 1: ex = exp(lrelu(el+er)); sum denominators ----
        float4 d4 = {0.f, 0.f, 0.f, 0.f};
        int s_my = 0;
        float4 ex_my = {0.f, 0.f, 0.f, 0.f};

        int i0 = beg + lane;
        if (i0 < end) {
            s_my = __ldg(&g_csr_src[i0]);
            float4 l4 = *(const float4*)(g_el + s_my * NH);
            ex_my.x = __expf(lrelu(l4.x + er4.x));
            ex_my.y = __expf(lrelu(l4.y + er4.y));
            ex_my.z = __expf(lrelu(l4.z + er4.z));
            ex_my.w = __expf(lrelu(l4.w + er4.w));
            d4 = ex_my;
            if (!small) *(float4*)(g_e + (size_t)i0 * NH) = ex_my;
        }
        if (!small) {
            for (int i = i0 + 32; i < end; i += 32) {
                int s = __ldg(&g_csr_src[i]);
                float4 l4 = *(const float4*)(g_el + s * NH);
                float4 ex;
                ex.x = __expf(lrelu(l4.x + er4.x));
                ex.y = __expf(lrelu(l4.y + er4.y));
                ex.z = __expf(lrelu(l4.z + er4.z));
                ex.w = __expf(lrelu(l4.w + er4.w));
                d4.x += ex.x; d4.y += ex.y; d4.z += ex.z; d4.w += ex.w;
                *(float4*)(g_e + (size_t)i * NH) = ex;
            }
        }
#pragma unroll
        for (int off = 16; off; off >>= 1) {
            d4.x += __shfl_xor_sync(0xffffffffu, d4.x, off);
            d4.y += __shfl_xor_sync(0xffffffffu, d4.y, off);
            d4.z += __shfl_xor_sync(0xffffffffu, d4.z, off);
            d4.w += __shfl_xor_sync(0xffffffffu, d4.w, off);
        }
        float4 rd4;
        rd4.x = __frcp_rn(d4.x); rd4.y = __frcp_rn(d4.y);
        rd4.z = __frcp_rn(d4.z); rd4.w = __frcp_rn(d4.w);

        // ---- phase 2: aggregation via smem-staged (src, alpha) ----
        if (small) {
            if (lane < deg) {
                ssrc[w][lane] = s_my;
                salpha[w][lane][0] = ex_my.x * rd4.x;
                salpha[w][lane][1] = ex_my.y * rd4.y;
                salpha[w][lane][2] = ex_my.z * rd4.z;
                salpha[w][lane][3] = ex_my.w * rd4.w;
            }
            __syncwarp();
            for (int i = 0; i < deg; i++) {
                int si = ssrc[w][i];
                float alpha = salpha[w][i][h];
                float4 f = *(const float4*)(g_feat + (size_t)si * HD + lane * 4);
                acc.x = fmaf(f.x, alpha, acc.x);
                acc.y = fmaf(f.y, alpha, acc.y);
                acc.z = fmaf(f.z, alpha, acc.z);
                acc.w = fmaf(f.w, alpha, acc.w);
            }
        } else {
            for (int base = beg; base < end; base += 32) {
                int n = min(32, end - base);
                if (lane < n) {
                    int i = base + lane;
                    int s = __ldg(&g_csr_src[i]);
                    float4 ex = *(const float4*)(g_e + (size_t)i * NH);
                    ssrc[w][lane] = s;
                    salpha[w][lane][0] = ex.x * rd4.x;
                    salpha[w][lane][1] = ex.y * rd4.y;
                    salpha[w][lane][2] = ex.z * rd4.z;
                    salpha[w][lane][3] = ex.w * rd4.w;
                }
                __syncwarp();
                for (int i = 0; i < n; i++) {
                    int si = ssrc[w][i];
                    float alpha = salpha[w][i][h];
                    float4 f = *(const float4*)(g_feat + (size_t)si * HD + lane * 4);
                    acc.x = fmaf(f.x, alpha, acc.x);
                    acc.y = fmaf(f.y, alpha, acc.y);
                    acc.z = fmaf(f.z, alpha, acc.z);
                    acc.w = fmaf(f.w, alpha, acc.w);
                }
                __syncwarp();
            }
        }
    }

    // ---- epilogue: ELU (+ head-mean for layer 2) ----
    acc.x = (acc.x > 0.f) ? acc.x : expm1f(acc.x);
    acc.y = (acc.y > 0.f) ? acc.y : expm1f(acc.y);
    acc.z = (acc.z > 0.f) ? acc.z : expm1f(acc.z);
    acc.w = (acc.w > 0.f) ? acc.w : expm1f(acc.w);

    if (out == nullptr) {
        *(float4*)(g_h1 + (size_t)t * HD + lane * 4) = acc;
    } else {
        // sum over heads: lanes l, l^8, l^16, l^24 hold same dims across heads
#pragma unroll
        for (int off = 8; off <= 16; off <<= 1) {
            acc.x += __shfl_xor_sync(0xffffffffu, acc.x, off);
            acc.y += __shfl_xor_sync(0xffffffffu, acc.y, off);
            acc.z += __shfl_xor_sync(0xffffffffu, acc.z, off);
            acc.w += __shfl_xor_sync(0xffffffffu, acc.w, off);
        }
        if (lane < 8) {
            float4 o;
            o.x = 0.25f * acc.x; o.y = 0.25f * acc.y;
            o.z = 0.25f * acc.z; o.w = 0.25f * acc.w;
            *(float4*)(out + t * ND + lane * 4) = o;
        }
    }
}

// ---------------- launch ----------------------------------------------------
extern "C" void kernel_launch(void* const* d_in, const int* in_sizes, int n_in,
                              void* d_out, int out_size)
{
    const float* x   = (const float*)d_in[0];
    const void*  src = d_in[1];
    const void*  dst = d_in[2];
    const float* W1  = (const float*)d_in[3];
    const float* al1 = (const float*)d_in[4];
    const float* ar1 = (const float*)d_in[5];
    const float* W2  = (const float*)d_in[6];
    const float* al2 = (const float*)d_in[7];
    const float* ar2 = (const float*)d_in[8];
    float* out = (float*)d_out;

    const int edge_blocks = (EE + 255) / 256;
    const int node_blocks = (NN + 255) / 256;
    const int scan_blocks = (NN + SCAN_B - 1) / SCAN_B;   // 98
    const int gemm_blocks = (NN + NPB - 1) / NPB;
    const int gat_blocks  = (NN + 7) / 8;

    // ---- CSR build ----
    zero_cnt_kernel<<<node_blocks, 256>>>((const long long*)src);
    convert_kernel<<<edge_blocks, 256>>>(dst);
    scan1_kernel<<<scan_blocks, SCAN_B>>>();
    scan2_kernel<<<1, 128>>>(scan_blocks);
    scan3_kernel<<<node_blocks, 256>>>();
    scatter_kernel<<<edge_blocks, 256>>>(src);

    // ---- layer 1 ----
    gemm_kernel<<<gemm_blocks, 128>>>(x, W1, al1, ar1);
    gat_edge_kernel<<<gat_blocks, 256>>>(nullptr);

    // ---- layer 2 ----
    gemm_kernel<<<gemm_blocks, 128>>>(nullptr, W2, al2, ar2);
    gat_edge_kernel<<<gat_blocks, 256>>>(out);

    (void)in_sizes; (void)n_in; (void)out_size;
}